// round 14
// baseline (speedup 1.0000x reference)
#include <cuda_runtime.h>
#include <math.h>

// Problem constants
#define BB 64      // batch B
#define TT 256     // T
#define EE 64      // E (layer0 feature dim)
#define RR 4       // rel_dim
#define NSTACK 8   // n_stack
#define NEG_INF (-1e30f)
#define NPART 256  // gram partials (128 blocks x 2 combined pairs)
#define NBLK 128   // persistent grid size (1 block/SM, all resident)

// -------- scratch (__device__ globals; no allocations) --------
__device__ float    g_partial[NPART * BB * BB];  // split-K gram partials (4MB)
__device__ float    g_x1[BB * TT * RR];          // layer0 output
__device__ unsigned g_flags[NBLK];               // per-block arrival flags
__device__ unsigned g_rel;                       // release word

// ---------------------------------------------------------------------
// Flag-array grid barrier (all NBLK blocks co-resident: 1024 thr = 1
// block/SM, 128 < 148 SMs). Arrival = one STG to a private flag (no
// atomic convoy). Block 0 warp 0 polls all flags, publishes release.
// Monotone generation (base read at launch start) survives graph replays.
// ---------------------------------------------------------------------
__device__ __forceinline__ void grid_sync2(int bid, unsigned target) {
    __syncthreads();
    if (threadIdx.x < 32) {
        if (threadIdx.x == 0) {
            __threadfence();                              // release phase data
            ((volatile unsigned*)g_flags)[bid] = target;  // private flag: no contention
        }
        if (bid == 0) {
            bool done = false;
            while (!done) {
                unsigned f0 = ((volatile unsigned*)g_flags)[threadIdx.x];
                unsigned f1 = ((volatile unsigned*)g_flags)[threadIdx.x + 32];
                unsigned f2 = ((volatile unsigned*)g_flags)[threadIdx.x + 64];
                unsigned f3 = ((volatile unsigned*)g_flags)[threadIdx.x + 96];
                bool ok = (int)(f0 - target) >= 0 && (int)(f1 - target) >= 0 &&
                          (int)(f2 - target) >= 0 && (int)(f3 - target) >= 0;
                done = __all_sync(0xFFFFFFFFu, ok);
            }
            if (threadIdx.x == 0) {
                __threadfence();
                ((volatile unsigned*)&g_rel)[0] = target;
            }
        } else if (threadIdx.x == 0) {
            while ((int)(((volatile unsigned*)&g_rel)[0] - target) < 0) {}
        }
        if (threadIdx.x == 0) __threadfence();            // acquire
    }
    __syncthreads();
}

// =====================================================================
// Shared-memory sparsemax + pooling-group state.
// =====================================================================
struct Epi {
    float        z[BB];
    float        zs[BB];
    float        av[BB];
    unsigned int keys[BB];
    unsigned int gkey[BB];
    float        gcnt[BB];
    int          ng;
};

// Single-warp sparsemax (exact reference semantics) + merged pooling-
// window groups (SAME pool=4 over neighbor axis). Executed by warp 0
// ONLY (caller guards tid<32); caller does __syncthreads before (z
// published) and after (results published). Lane l owns elements
// e0 = l and e1 = l + 32.
__device__ __forceinline__ void sparsemax_groups_w0(Epi* S) {
    const int l = threadIdx.x;                 // 0..31
    const float z0 = S->z[l], z1 = S->z[l + 32];

    // rank (descending, index tiebreak) -> scatter into sorted zs
    int r0 = 0, r1 = 0;
#pragma unroll
    for (int j = 0; j < BB; ++j) {
        const float zj = S->z[j];
        r0 += (zj > z0) || (zj == z0 && j < l);
        r1 += (zj > z1) || (zj == z1 && j < l + 32);
    }
    S->zs[r0] = z0;
    S->zs[r1] = z1;
    __syncwarp();

    // inclusive cumsum over sorted values (two 32-chunks, shfl scan)
    const float v0 = S->zs[l], v1 = S->zs[l + 32];
    float c0 = v0, c1 = v1;
#pragma unroll
    for (int d = 1; d < 32; d <<= 1) {
        const float n0 = __shfl_up_sync(0xFFFFFFFFu, c0, d);
        const float n1 = __shfl_up_sync(0xFFFFFFFFu, c1, d);
        if (l >= d) { c0 += n0; c1 += n1; }
    }
    c1 += __shfl_sync(0xFFFFFFFFu, c0, 31);

    // support size + tau
    const int sup0 = (1.0f + (float)(l + 1)  * v0 > c0) ? 1 : 0;
    const int sup1 = (1.0f + (float)(l + 33) * v1 > c1) ? 1 : 0;
    const int ksel = __popc(__ballot_sync(0xFFFFFFFFu, sup0)) +
                     __popc(__ballot_sync(0xFFFFFFFFu, sup1));
    const float ca = __shfl_sync(0xFFFFFFFFu, c0, (ksel - 1) & 31);
    const float cb = __shfl_sync(0xFFFFFFFFu, c1, (ksel - 33) & 31);
    const float cums = (ksel <= 32) ? ca : cb;
    const float tau = (cums - 1.0f) / (float)ksel;

    const float a0 = fmaxf(z0 - tau, 0.0f);
    const float a1 = fmaxf(z1 - tau, 0.0f);
    S->av[l] = a0;
    S->av[l + 32] = a1;
    __syncwarp();

    // per-window support-member keys for e0 and e1
    unsigned int k0, k1;
    {
        const int e = l;
        const int lo = (e - 1 > 0) ? e - 1 : 0;
        const int hi = (e + 2 < BB - 1) ? e + 2 : BB - 1;
        int nm = 0; unsigned int key = 0u;
        for (int bp = lo; bp <= hi; ++bp)
            if (S->av[bp] > 0.0f) { key |= ((unsigned)bp) << (6 * nm); nm++; }
        const int wsz = hi - lo + 1;
        if (nm == 0) key = 0xFFFFFFFFu;
        else key |= ((unsigned)nm << 24) | ((nm < wsz ? 1u : 0u) << 28);
        k0 = key;
    }
    {
        const int e = l + 32;
        const int lo = e - 1;                          // e>=32, no clip low
        const int hi = (e + 2 < BB - 1) ? e + 2 : BB - 1;
        int nm = 0; unsigned int key = 0u;
        for (int bp = lo; bp <= hi; ++bp)
            if (S->av[bp] > 0.0f) { key |= ((unsigned)bp) << (6 * nm); nm++; }
        const int wsz = hi - lo + 1;
        if (nm == 0) key = 0xFFFFFFFFu;
        else key |= ((unsigned)nm << 24) | ((nm < wsz ? 1u : 0u) << 28);
        k1 = key;
    }
    S->keys[l] = k0;
    S->keys[l + 32] = k1;
    __syncwarp();

    // duplicate counts + leader election + ballot compaction
    int cnt0 = 0, cnt1 = 0;
    int lead0 = (k0 != 0xFFFFFFFFu), lead1 = (k1 != 0xFFFFFFFFu);
#pragma unroll
    for (int j = 0; j < BB; ++j) {
        const unsigned kj = S->keys[j];
        cnt0 += (kj == k0); if (kj == k0 && j < l)      lead0 = (k0 != 0xFFFFFFFFu) ? 0 : lead0;
        cnt1 += (kj == k1); if (kj == k1 && j < l + 32) lead1 = (k1 != 0xFFFFFFFFu) ? 0 : lead1;
    }
    if (k0 == 0xFFFFFFFFu) lead0 = 0;
    if (k1 == 0xFFFFFFFFu) lead1 = 0;
    const unsigned lb0 = __ballot_sync(0xFFFFFFFFu, lead0);
    const unsigned lb1 = __ballot_sync(0xFFFFFFFFu, lead1);
    if (lead0) {
        const int pos = __popc(lb0 & ((1u << l) - 1u));
        S->gkey[pos] = k0; S->gcnt[pos] = (float)cnt0;
    }
    if (lead1) {
        const int pos = __popc(lb0) + __popc(lb1 & ((1u << l) - 1u));
        S->gkey[pos] = k1; S->gcnt[pos] = (float)cnt1;
    }
    if (l == 0) S->ng = __popc(lb0) + __popc(lb1);
}

// =====================================================================
// ONE persistent kernel, 128 blocks x 1024 threads, 3 phases.
// =====================================================================
__global__ __launch_bounds__(1024) void gcn_mega_kernel(
    const float* __restrict__ x,
    const float* __restrict__ W0,
    const float* __restrict__ W1,
    const float* __restrict__ Wp,
    float* __restrict__ outp)
{
    __shared__ float Xs[BB][130];      // stride 130: float2-k conflict-free
    __shared__ Epi S;
    __shared__ float red[16][BB];
    __shared__ float W_s[EE * RR];
    __shared__ float4 xrow4[TT * RR / 4];
    __shared__ float msm[32][4];
    __shared__ unsigned s_base;

    const int bid = blockIdx.x;
    const int tid = threadIdx.x;       // 0..1023

    if (tid == 0) s_base = ((volatile unsigned*)g_flags)[bid];

    // ---------------- Phase A: layer-0 gram ----------------
    {
        const float4* X4 = (const float4*)(x) + bid * 32;    // 4096 float4/row
        for (int i = tid; i < BB * 32; i += 1024) {
            const int r = i >> 5, c4 = i & 31;
            const float4 v = X4[r * 4096 + c4];
            float* rowp = &Xs[r][c4 * 4];
            rowp[0] = v.x; rowp[1] = v.y; rowp[2] = v.z; rowp[3] = v.w;
        }
        __syncthreads();               // also publishes s_base

        const int quarter = tid >> 8;          // 0..3: K sub-range (32 wide)
        const int t256    = tid & 255;
        const int tx = t256 & 15, ty = t256 >> 4;
        const int kbase = quarter * 32;

        float acc[4][4];
#pragma unroll
        for (int i = 0; i < 4; ++i)
#pragma unroll
            for (int j = 0; j < 4; ++j) acc[i][j] = 0.f;

#pragma unroll 8
        for (int k2 = 0; k2 < 16; ++k2) {
            float2 a[4], b[4];
#pragma unroll
            for (int i = 0; i < 4; ++i)
                a[i] = *(const float2*)&Xs[ty + 16 * i][kbase + 2 * k2];
#pragma unroll
            for (int j = 0; j < 4; ++j)
                b[j] = *(const float2*)&Xs[tx + 16 * j][kbase + 2 * k2];
#pragma unroll
            for (int i = 0; i < 4; ++i)
#pragma unroll
                for (int j = 0; j < 4; ++j) {
                    acc[i][j] = fmaf(a[i].x, b[j].x, acc[i][j]);
                    acc[i][j] = fmaf(a[i].y, b[j].y, acc[i][j]);
                }
        }
        __syncthreads();               // Xs dead; reuse as combine buffers

        // combine quarter pairs (0,1) and (2,3) -> 2 partials per block
        float* buf = &Xs[0][0];        // 8320 floats available, need 8192
        if (quarter & 1) {
            float* b = buf + (quarter >> 1) * 4096;
#pragma unroll
            for (int i = 0; i < 4; ++i)
#pragma unroll
                for (int j = 0; j < 4; ++j)
                    b[(ty + 16 * i) * BB + (tx + 16 * j)] = acc[i][j];
        }
        __syncthreads();
        if (!(quarter & 1)) {
            const float* b = buf + (quarter >> 1) * 4096;
            float* dst = g_partial + (bid * 2 + (quarter >> 1)) * (BB * BB);
#pragma unroll
            for (int i = 0; i < 4; ++i)
#pragma unroll
                for (int j = 0; j < 4; ++j) {
                    const int idx = (ty + 16 * i) * BB + (tx + 16 * j);
                    dst[idx] = acc[i][j] + b[idx];
                }
        }
    }

    grid_sync2(bid, s_base + 1);

    // ---------------- Phase B: layer-0 tail ----------------
    {
        const int row  = bid >> 1;
        const int half = bid & 1;

        {   // split-K reduce: 16 sub-reducers per column, coalesced
            const int c = tid & 63, sub = tid >> 6;
            float s = 0.f;
#pragma unroll
            for (int p = sub; p < NPART; p += 16)
                s += g_partial[p * (BB * BB) + row * BB + c];
            red[sub][c] = s;
        }
        if (tid < EE * RR) W_s[tid] = W0[tid];
        __syncthreads();
        if (tid < BB) {
            float t = 0.f;
#pragma unroll
            for (int q = 0; q < 16; ++q) t += red[q][tid];
            S.z[tid] = t * (1.0f / (float)TT);
        }
        __syncthreads();
        if (tid < 32) sparsemax_groups_w0(&S);
        __syncthreads();

        // pool0: 32 warps cover 128 t's of this half, 4 t's per warp
        const int lane = tid & 31, w = tid >> 5;
        const int ng = S.ng;
        const int tbase = half * 128 + w * 4;
        float acc0[4], acc1[4];
#pragma unroll
        for (int i = 0; i < 4; ++i) { acc0[i] = 0.f; acc1[i] = 0.f; }

        for (int g = 0; g < ng; ++g) {
            const unsigned int key = S.gkey[g];
            const float cnt = S.gcnt[g];
            const int nm = (key >> 24) & 7;
            unsigned int mm = key;
            float m0[4], m1[4];
#pragma unroll
            for (int i = 0; i < 4; ++i) { m0[i] = NEG_INF; m1[i] = NEG_INF; }
            for (int u = 0; u < nm; ++u) {
                const int bp = mm & 63; mm >>= 6;
                const float avv = S.av[bp];
                const float* xp = x + bp * (TT * EE) + tbase * EE + lane;
#pragma unroll
                for (int i = 0; i < 4; ++i) {
                    m0[i] = fmaxf(m0[i], avv * xp[i * EE]);
                    m1[i] = fmaxf(m1[i], avv * xp[i * EE + 32]);
                }
            }
            const float zf = (key >> 28) ? 0.f : NEG_INF;
#pragma unroll
            for (int i = 0; i < 4; ++i) {
                acc0[i] += cnt * fmaxf(m0[i], zf);
                acc1[i] += cnt * fmaxf(m1[i], zf);
            }
        }

        // out[row, t, r] = relu(sum_e agg_e * W0[e][r]) via warp butterfly
#pragma unroll
        for (int i = 0; i < 4; ++i) {
            float res = 0.f;
#pragma unroll
            for (int rout = 0; rout < RR; ++rout) {
                float p = acc0[i] * W_s[lane * RR + rout] + acc1[i] * W_s[(lane + 32) * RR + rout];
                p += __shfl_xor_sync(0xFFFFFFFFu, p, 1);
                p += __shfl_xor_sync(0xFFFFFFFFu, p, 2);
                p += __shfl_xor_sync(0xFFFFFFFFu, p, 4);
                p += __shfl_xor_sync(0xFFFFFFFFu, p, 8);
                p += __shfl_xor_sync(0xFFFFFFFFu, p, 16);
                if (lane == rout) res = p;
            }
            if (lane < RR) g_x1[(row * TT + tbase + i) * RR + lane] = fmaxf(res, 0.f);
        }
    }

    grid_sync2(bid, s_base + 2);

    // ---------------- Phase C: layer-1 + tail (blocks 0..63) ----------
    if (bid >= BB) return;
    {
        const int row = bid;
        const float4* x14 = (const float4*)g_x1;

        if (tid < 256) xrow4[tid] = x14[row * 256 + tid];
        if (tid < RR * RR) W_s[tid] = W1[tid];
        __syncthreads();

        {   // gram row: 16 subs per column, 16 float4 each
            const int col = tid >> 4, sub = tid & 15;
            const float4* base = x14 + col * 256;
            float s0 = 0.f, s1 = 0.f;
#pragma unroll
            for (int i = 0; i < 16; i += 2) {
                const float4 b0 = base[(i + 0) * 16 + sub];
                const float4 b1 = base[(i + 1) * 16 + sub];
                const float4 a0 = xrow4[(i + 0) * 16 + sub];
                const float4 a1 = xrow4[(i + 1) * 16 + sub];
                s0 += a0.x * b0.x + a0.y * b0.y + a0.z * b0.z + a0.w * b0.w;
                s1 += a1.x * b1.x + a1.y * b1.y + a1.z * b1.z + a1.w * b1.w;
            }
            red[sub][col] = s0 + s1;
        }
        __syncthreads();
        if (tid < BB) {
            float t = 0.f;
#pragma unroll
            for (int q = 0; q < 16; ++q) t += red[q][tid];
            S.z[tid] = t * (1.0f / (float)TT);
        }
        __syncthreads();
        if (tid < 32) sparsemax_groups_w0(&S);
        __syncthreads();

        // pool1 + W1 + relu; one t per thread (r = tid&3, t = tid>>2)
        const int r = tid & 3;
        const int t = tid >> 2;    // 0..255
        const int ng = S.ng;
        const float* x1f = (const float*)g_x1;
        const int off = t * RR + r;

        float acc = 0.f;
        for (int g = 0; g < ng; ++g) {
            const unsigned int key = S.gkey[g];
            const int nm = (key >> 24) & 7;
            unsigned int mm = key;
            float m = NEG_INF;
            for (int u = 0; u < nm; ++u) {
                const int bp = mm & 63; mm >>= 6;
                m = fmaxf(m, S.av[bp] * x1f[bp * (TT * RR) + off]);
            }
            if (key >> 28) m = fmaxf(m, 0.f);
            acc += S.gcnt[g] * m;
        }
        float msum = 0.f;
#pragma unroll
        for (int rout = 0; rout < RR; ++rout) {
            float p = acc * W_s[r * RR + rout];
            p += __shfl_xor_sync(0xFFFFFFFFu, p, 1);
            p += __shfl_xor_sync(0xFFFFFFFFu, p, 2);
            if (r == rout) msum = p;
        }
        msum = fmaxf(msum, 0.f);   // relu; per-thread contribution to mean

        // reduce over the 8 t-slots within each warp (r preserved)
        msum += __shfl_xor_sync(0xFFFFFFFFu, msum, 4);
        msum += __shfl_xor_sync(0xFFFFFFFFu, msum, 8);
        msum += __shfl_xor_sync(0xFFFFFFFFu, msum, 16);
        if ((tid & 31) < 4) msm[tid >> 5][r] = msum;
        __syncthreads();
        if (tid < 4) {
            float p = 0.f;
#pragma unroll
            for (int wg = 0; wg < 32; ++wg) p += msm[wg][tid];
            msm[0][tid] = p * (1.0f / (float)TT);
        }
        __syncthreads();
        if (tid == 0) {
            float logit[NSTACK];
            float mx = NEG_INF;
#pragma unroll
            for (int n = 0; n < NSTACK; ++n) {
                float p = 0.f;
#pragma unroll
                for (int rr = 0; rr < RR; ++rr) p += msm[0][rr] * Wp[rr * NSTACK + n];
                logit[n] = p;
                mx = fmaxf(mx, p);
            }
            float se = 0.f;
#pragma unroll
            for (int n = 0; n < NSTACK; ++n) { logit[n] = expf(logit[n] - mx); se += logit[n]; }
            const float inv = 1.0f / se;
#pragma unroll
            for (int n = 0; n < NSTACK; ++n) outp[row * NSTACK + n] = logit[n] * inv;
        }
    }
}

// =====================================================================
extern "C" void kernel_launch(void* const* d_in, const int* in_sizes, int n_in,
                              void* d_out, int out_size) {
    const float* x  = (const float*)d_in[0];  // [64,256,64]
    const float* W0 = (const float*)d_in[1];  // [64,4]
    const float* W1 = (const float*)d_in[2];  // [4,4]
    const float* Wp = (const float*)d_in[3];  // [4,8]
    float* out = (float*)d_out;               // [64,8]

    gcn_mega_kernel<<<NBLK, 1024>>>(x, W0, W1, Wp, out);
}

// round 15
// speedup vs baseline: 1.9145x; 1.9145x over previous
#include <cuda_runtime.h>
#include <math.h>

// Problem constants
#define BB 64      // batch B
#define TT 256     // T
#define EE 64      // E (layer0 feature dim)
#define RR 4       // rel_dim
#define NSTACK 8   // n_stack
#define NEG_INF (-1e30f)
#define NPART 256  // gram partials (128 blocks x 2 combined pairs)
#define NBLK 128   // persistent grid size (1 block/SM, all resident)

// -------- scratch (__device__ globals; no allocations) --------
__device__ float    g_partial[NPART * BB * BB];  // split-K gram partials (4MB)
__device__ float    g_x1[BB * TT * RR];          // layer0 output
__device__ int      g_bar_count = 0;             // grid barrier state
__device__ unsigned g_bar_gen   = 0;

// ---------------------------------------------------------------------
// Atomic generation grid barrier (measured good in R13). Safe: all NBLK
// blocks co-resident (1024 thr -> 1 block/SM, 128 < 148 SMs). The last
// arriver opens the gate, so release latency = one atomic round trip.
// Generation counter is monotone across graph replays.
// ---------------------------------------------------------------------
__device__ __forceinline__ void grid_sync() {
    __syncthreads();
    if (threadIdx.x == 0) {
        __threadfence();                                  // release phase data
        const unsigned gen = *(volatile unsigned*)&g_bar_gen;
        if (atomicAdd(&g_bar_count, 1) == NBLK - 1) {
            g_bar_count = 0;
            __threadfence();
            *(volatile unsigned*)&g_bar_gen = gen + 1;    // open the gate
        } else {
            while (*(volatile unsigned*)&g_bar_gen == gen) {}
        }
        __threadfence();                                  // acquire
    }
    __syncthreads();
}

// =====================================================================
// Shared-memory sparsemax + pooling-group state.
// =====================================================================
struct Epi {
    float        z[BB];
    float        zs[BB];
    float        av[BB];
    unsigned int keys[BB];
    unsigned int gkey[BB];
    float        gcnt[BB];
    int          ng;
};

// Single-warp sparsemax (exact reference semantics) + merged pooling-
// window groups (SAME pool=4 over neighbor axis). Executed by warp 0
// ONLY (caller guards tid<32); caller does __syncthreads before (z
// published) and after (results published). Lane l owns elements
// e0 = l and e1 = l + 32.
__device__ __forceinline__ void sparsemax_groups_w0(Epi* S) {
    const int l = threadIdx.x;                 // 0..31
    const float z0 = S->z[l], z1 = S->z[l + 32];

    // rank (descending, index tiebreak) -> scatter into sorted zs
    int r0 = 0, r1 = 0;
#pragma unroll
    for (int j = 0; j < BB; ++j) {
        const float zj = S->z[j];
        r0 += (zj > z0) || (zj == z0 && j < l);
        r1 += (zj > z1) || (zj == z1 && j < l + 32);
    }
    S->zs[r0] = z0;
    S->zs[r1] = z1;
    __syncwarp();

    // inclusive cumsum over sorted values (two 32-chunks, shfl scan)
    const float v0 = S->zs[l], v1 = S->zs[l + 32];
    float c0 = v0, c1 = v1;
#pragma unroll
    for (int d = 1; d < 32; d <<= 1) {
        const float n0 = __shfl_up_sync(0xFFFFFFFFu, c0, d);
        const float n1 = __shfl_up_sync(0xFFFFFFFFu, c1, d);
        if (l >= d) { c0 += n0; c1 += n1; }
    }
    c1 += __shfl_sync(0xFFFFFFFFu, c0, 31);

    // support size + tau
    const int sup0 = (1.0f + (float)(l + 1)  * v0 > c0) ? 1 : 0;
    const int sup1 = (1.0f + (float)(l + 33) * v1 > c1) ? 1 : 0;
    const int ksel = __popc(__ballot_sync(0xFFFFFFFFu, sup0)) +
                     __popc(__ballot_sync(0xFFFFFFFFu, sup1));
    const float ca = __shfl_sync(0xFFFFFFFFu, c0, (ksel - 1) & 31);
    const float cb = __shfl_sync(0xFFFFFFFFu, c1, (ksel - 33) & 31);
    const float cums = (ksel <= 32) ? ca : cb;
    const float tau = (cums - 1.0f) / (float)ksel;

    const float a0 = fmaxf(z0 - tau, 0.0f);
    const float a1 = fmaxf(z1 - tau, 0.0f);
    S->av[l] = a0;
    S->av[l + 32] = a1;
    __syncwarp();

    // per-window support-member keys for e0 and e1
    unsigned int k0, k1;
    {
        const int e = l;
        const int lo = (e - 1 > 0) ? e - 1 : 0;
        const int hi = (e + 2 < BB - 1) ? e + 2 : BB - 1;
        int nm = 0; unsigned int key = 0u;
        for (int bp = lo; bp <= hi; ++bp)
            if (S->av[bp] > 0.0f) { key |= ((unsigned)bp) << (6 * nm); nm++; }
        const int wsz = hi - lo + 1;
        if (nm == 0) key = 0xFFFFFFFFu;
        else key |= ((unsigned)nm << 24) | ((nm < wsz ? 1u : 0u) << 28);
        k0 = key;
    }
    {
        const int e = l + 32;
        const int lo = e - 1;                          // e>=32, no clip low
        const int hi = (e + 2 < BB - 1) ? e + 2 : BB - 1;
        int nm = 0; unsigned int key = 0u;
        for (int bp = lo; bp <= hi; ++bp)
            if (S->av[bp] > 0.0f) { key |= ((unsigned)bp) << (6 * nm); nm++; }
        const int wsz = hi - lo + 1;
        if (nm == 0) key = 0xFFFFFFFFu;
        else key |= ((unsigned)nm << 24) | ((nm < wsz ? 1u : 0u) << 28);
        k1 = key;
    }
    S->keys[l] = k0;
    S->keys[l + 32] = k1;
    __syncwarp();

    // duplicate counts + leader election + ballot compaction
    int cnt0 = 0, cnt1 = 0;
    int lead0 = (k0 != 0xFFFFFFFFu), lead1 = (k1 != 0xFFFFFFFFu);
#pragma unroll
    for (int j = 0; j < BB; ++j) {
        const unsigned kj = S->keys[j];
        cnt0 += (kj == k0); if (kj == k0 && j < l)      lead0 = (k0 != 0xFFFFFFFFu) ? 0 : lead0;
        cnt1 += (kj == k1); if (kj == k1 && j < l + 32) lead1 = (k1 != 0xFFFFFFFFu) ? 0 : lead1;
    }
    if (k0 == 0xFFFFFFFFu) lead0 = 0;
    if (k1 == 0xFFFFFFFFu) lead1 = 0;
    const unsigned lb0 = __ballot_sync(0xFFFFFFFFu, lead0);
    const unsigned lb1 = __ballot_sync(0xFFFFFFFFu, lead1);
    if (lead0) {
        const int pos = __popc(lb0 & ((1u << l) - 1u));
        S->gkey[pos] = k0; S->gcnt[pos] = (float)cnt0;
    }
    if (lead1) {
        const int pos = __popc(lb0) + __popc(lb1 & ((1u << l) - 1u));
        S->gkey[pos] = k1; S->gcnt[pos] = (float)cnt1;
    }
    if (l == 0) S->ng = __popc(lb0) + __popc(lb1);
}

// =====================================================================
// ONE persistent kernel, 128 blocks x 1024 threads, 3 phases.
// =====================================================================
__global__ __launch_bounds__(1024) void gcn_mega_kernel(
    const float* __restrict__ x,
    const float* __restrict__ W0,
    const float* __restrict__ W1,
    const float* __restrict__ Wp,
    float* __restrict__ outp)
{
    __shared__ float Xs[BB][130];      // stride 130: float2-k conflict-free
    __shared__ Epi S;
    __shared__ float red[16][BB];
    __shared__ float W_s[EE * RR];
    __shared__ float4 xrow4[TT * RR / 4];
    __shared__ float msm[32][4];

    const int bid = blockIdx.x;
    const int tid = threadIdx.x;       // 0..1023

    // ---------------- Phase A: layer-0 gram ----------------
    {
        const float4* X4 = (const float4*)(x) + bid * 32;    // 4096 float4/row
        for (int i = tid; i < BB * 32; i += 1024) {
            const int r = i >> 5, c4 = i & 31;
            const float4 v = X4[r * 4096 + c4];
            float* rowp = &Xs[r][c4 * 4];
            rowp[0] = v.x; rowp[1] = v.y; rowp[2] = v.z; rowp[3] = v.w;
        }
        __syncthreads();

        const int quarter = tid >> 8;          // 0..3: K sub-range (32 wide)
        const int t256    = tid & 255;
        const int tx = t256 & 15, ty = t256 >> 4;
        const int kbase = quarter * 32;

        float acc[4][4];
#pragma unroll
        for (int i = 0; i < 4; ++i)
#pragma unroll
            for (int j = 0; j < 4; ++j) acc[i][j] = 0.f;

#pragma unroll 8
        for (int k2 = 0; k2 < 16; ++k2) {
            float2 a[4], b[4];
#pragma unroll
            for (int i = 0; i < 4; ++i)
                a[i] = *(const float2*)&Xs[ty + 16 * i][kbase + 2 * k2];
#pragma unroll
            for (int j = 0; j < 4; ++j)
                b[j] = *(const float2*)&Xs[tx + 16 * j][kbase + 2 * k2];
#pragma unroll
            for (int i = 0; i < 4; ++i)
#pragma unroll
                for (int j = 0; j < 4; ++j) {
                    acc[i][j] = fmaf(a[i].x, b[j].x, acc[i][j]);
                    acc[i][j] = fmaf(a[i].y, b[j].y, acc[i][j]);
                }
        }
        __syncthreads();               // Xs dead; reuse as combine buffers

        // combine quarter pairs (0,1) and (2,3) -> 2 partials per block
        float* buf = &Xs[0][0];        // 8320 floats available, need 8192
        if (quarter & 1) {
            float* b = buf + (quarter >> 1) * 4096;
#pragma unroll
            for (int i = 0; i < 4; ++i)
#pragma unroll
                for (int j = 0; j < 4; ++j)
                    b[(ty + 16 * i) * BB + (tx + 16 * j)] = acc[i][j];
        }
        __syncthreads();
        if (!(quarter & 1)) {
            const float* b = buf + (quarter >> 1) * 4096;
            float* dst = g_partial + (bid * 2 + (quarter >> 1)) * (BB * BB);
#pragma unroll
            for (int i = 0; i < 4; ++i)
#pragma unroll
                for (int j = 0; j < 4; ++j) {
                    const int idx = (ty + 16 * i) * BB + (tx + 16 * j);
                    dst[idx] = acc[i][j] + b[idx];
                }
        }
    }

    grid_sync();

    // ---------------- Phase B: layer-0 tail ----------------
    {
        const int row  = bid >> 1;
        const int half = bid & 1;

        {   // split-K reduce: 16 sub-reducers per column, coalesced
            const int c = tid & 63, sub = tid >> 6;
            float s = 0.f;
#pragma unroll
            for (int p = sub; p < NPART; p += 16)
                s += g_partial[p * (BB * BB) + row * BB + c];
            red[sub][c] = s;
        }
        if (tid < EE * RR) W_s[tid] = W0[tid];
        __syncthreads();
        if (tid < BB) {
            float t = 0.f;
#pragma unroll
            for (int q = 0; q < 16; ++q) t += red[q][tid];
            S.z[tid] = t * (1.0f / (float)TT);
        }
        __syncthreads();
        if (tid < 32) sparsemax_groups_w0(&S);
        __syncthreads();

        // pool0: 32 warps cover 128 t's of this half, 4 t's per warp
        const int lane = tid & 31, w = tid >> 5;
        const int ng = S.ng;
        const int tbase = half * 128 + w * 4;
        float acc0[4], acc1[4];
#pragma unroll
        for (int i = 0; i < 4; ++i) { acc0[i] = 0.f; acc1[i] = 0.f; }

        for (int g = 0; g < ng; ++g) {
            const unsigned int key = S.gkey[g];
            const float cnt = S.gcnt[g];
            const int nm = (key >> 24) & 7;
            unsigned int mm = key;
            float m0[4], m1[4];
#pragma unroll
            for (int i = 0; i < 4; ++i) { m0[i] = NEG_INF; m1[i] = NEG_INF; }
            for (int u = 0; u < nm; ++u) {
                const int bp = mm & 63; mm >>= 6;
                const float avv = S.av[bp];
                const float* xp = x + bp * (TT * EE) + tbase * EE + lane;
#pragma unroll
                for (int i = 0; i < 4; ++i) {
                    m0[i] = fmaxf(m0[i], avv * xp[i * EE]);
                    m1[i] = fmaxf(m1[i], avv * xp[i * EE + 32]);
                }
            }
            const float zf = (key >> 28) ? 0.f : NEG_INF;
#pragma unroll
            for (int i = 0; i < 4; ++i) {
                acc0[i] += cnt * fmaxf(m0[i], zf);
                acc1[i] += cnt * fmaxf(m1[i], zf);
            }
        }

        // out[row, t, r] = relu(sum_e agg_e * W0[e][r]) via warp butterfly
#pragma unroll
        for (int i = 0; i < 4; ++i) {
            float res = 0.f;
#pragma unroll
            for (int rout = 0; rout < RR; ++rout) {
                float p = acc0[i] * W_s[lane * RR + rout] + acc1[i] * W_s[(lane + 32) * RR + rout];
                p += __shfl_xor_sync(0xFFFFFFFFu, p, 1);
                p += __shfl_xor_sync(0xFFFFFFFFu, p, 2);
                p += __shfl_xor_sync(0xFFFFFFFFu, p, 4);
                p += __shfl_xor_sync(0xFFFFFFFFu, p, 8);
                p += __shfl_xor_sync(0xFFFFFFFFu, p, 16);
                if (lane == rout) res = p;
            }
            if (lane < RR) g_x1[(row * TT + tbase + i) * RR + lane] = fmaxf(res, 0.f);
        }
    }

    grid_sync();

    // ---------------- Phase C: layer-1 + tail (blocks 0..63) ----------
    if (bid >= BB) return;
    {
        const int row = bid;
        const float4* x14 = (const float4*)g_x1;

        if (tid < 256) xrow4[tid] = x14[row * 256 + tid];
        if (tid < RR * RR) W_s[tid] = W1[tid];
        __syncthreads();

        {   // gram row: 16 subs per column, 16 float4 each
            const int col = tid >> 4, sub = tid & 15;
            const float4* base = x14 + col * 256;
            float s0 = 0.f, s1 = 0.f;
#pragma unroll
            for (int i = 0; i < 16; i += 2) {
                const float4 b0 = base[(i + 0) * 16 + sub];
                const float4 b1 = base[(i + 1) * 16 + sub];
                const float4 a0 = xrow4[(i + 0) * 16 + sub];
                const float4 a1 = xrow4[(i + 1) * 16 + sub];
                s0 += a0.x * b0.x + a0.y * b0.y + a0.z * b0.z + a0.w * b0.w;
                s1 += a1.x * b1.x + a1.y * b1.y + a1.z * b1.z + a1.w * b1.w;
            }
            red[sub][col] = s0 + s1;
        }
        __syncthreads();
        if (tid < BB) {
            float t = 0.f;
#pragma unroll
            for (int q = 0; q < 16; ++q) t += red[q][tid];
            S.z[tid] = t * (1.0f / (float)TT);
        }
        __syncthreads();
        if (tid < 32) sparsemax_groups_w0(&S);
        __syncthreads();

        // pool1 + W1 + relu; one t per thread (r = tid&3, t = tid>>2)
        const int r = tid & 3;
        const int t = tid >> 2;    // 0..255
        const int ng = S.ng;
        const float* x1f = (const float*)g_x1;
        const int off = t * RR + r;

        float acc = 0.f;
        for (int g = 0; g < ng; ++g) {
            const unsigned int key = S.gkey[g];
            const int nm = (key >> 24) & 7;
            unsigned int mm = key;
            float m = NEG_INF;
            for (int u = 0; u < nm; ++u) {
                const int bp = mm & 63; mm >>= 6;
                m = fmaxf(m, S.av[bp] * x1f[bp * (TT * RR) + off]);
            }
            if (key >> 28) m = fmaxf(m, 0.f);
            acc += S.gcnt[g] * m;
        }
        float msum = 0.f;
#pragma unroll
        for (int rout = 0; rout < RR; ++rout) {
            float p = acc * W_s[r * RR + rout];
            p += __shfl_xor_sync(0xFFFFFFFFu, p, 1);
            p += __shfl_xor_sync(0xFFFFFFFFu, p, 2);
            if (r == rout) msum = p;
        }
        msum = fmaxf(msum, 0.f);   // relu; per-thread contribution to mean

        // reduce over the 8 t-slots within each warp (r preserved)
        msum += __shfl_xor_sync(0xFFFFFFFFu, msum, 4);
        msum += __shfl_xor_sync(0xFFFFFFFFu, msum, 8);
        msum += __shfl_xor_sync(0xFFFFFFFFu, msum, 16);
        if ((tid & 31) < 4) msm[tid >> 5][r] = msum;
        __syncthreads();
        if (tid < 4) {
            float p = 0.f;
#pragma unroll
            for (int wg = 0; wg < 32; ++wg) p += msm[wg][tid];
            msm[0][tid] = p * (1.0f / (float)TT);
        }
        __syncthreads();
        if (tid == 0) {
            float logit[NSTACK];
            float mx = NEG_INF;
#pragma unroll
            for (int n = 0; n < NSTACK; ++n) {
                float p = 0.f;
#pragma unroll
                for (int rr = 0; rr < RR; ++rr) p += msm[0][rr] * Wp[rr * NSTACK + n];
                logit[n] = p;
                mx = fmaxf(mx, p);
            }
            float se = 0.f;
#pragma unroll
            for (int n = 0; n < NSTACK; ++n) { logit[n] = expf(logit[n] - mx); se += logit[n]; }
            const float inv = 1.0f / se;
#pragma unroll
            for (int n = 0; n < NSTACK; ++n) outp[row * NSTACK + n] = logit[n] * inv;
        }
    }
}

// =====================================================================
extern "C" void kernel_launch(void* const* d_in, const int* in_sizes, int n_in,
                              void* d_out, int out_size) {
    const float* x  = (const float*)d_in[0];  // [64,256,64]
    const float* W0 = (const float*)d_in[1];  // [64,4]
    const float* W1 = (const float*)d_in[2];  // [4,4]
    const float* Wp = (const float*)d_in[3];  // [4,8]
    float* out = (float*)d_out;               // [64,8]

    gcn_mega_kernel<<<NBLK, 1024>>>(x, W0, W1, Wp, out);
}